// round 9
// baseline (speedup 1.0000x reference)
#include <cuda_runtime.h>
#include <math_constants.h>
#include <cfloat>

// Problem constants (B=2, L=256, A=12, C=32, K=30)
#define NB 2
#define NL 256
#define NA 12
#define NATOM 3072          // NL*NA
#define NC 32
#define KNB 30
#define BIGD 1000000.0f
#define EMPTY_BITS 0xFFFFFFFFu
#define POISON 1.0e18f               // masked-atom coordinate (d2 -> 3e36 exactly)

// Output layout (all float32, concatenated in reference tuple order)
#define O_COORDS 0                       // (B, NATOM, 3)  -> 18432
#define O_MASK   (NB*NATOM*3)            // (B, NATOM)     -> 6144
#define O_ENC    (O_MASK + NB*NATOM)     // (B, NATOM, 32) -> 196608
#define O_DIST   (O_ENC + NB*NATOM*NC)   // (B, NATOM, 30) -> 184320
#define O_IDX    (O_DIST + NB*NATOM*KNB) // (B, NATOM, 30) -> 184320

#define WARPS 6              // rows (queries) per block
#define THR (WARPS * 32)     // 192
#define TPAD 97              // padded key-slice stride (32*97 floats per warp)
#define NT 96                // candidates per lane/column (3072/32)

__device__ float4 g_atoms[NB * NATOM];   // poisoned {x,y,z,mask}, 98 KB
__device__ float  g_A[NB * NC];          // rstd * scale
__device__ float  g_B[NB * NC];          // shift - mean * rstd * scale

// ---------------------------------------------------------------------------
// Prep: block 0 computes graph-norm coefs; all blocks poison the atom table.
// ---------------------------------------------------------------------------
#define PREP_BLOCKS 25
__global__ void prep_kernel(const float* __restrict__ coords,
                            const int* __restrict__ mask,
                            const float* __restrict__ T,
                            const float* __restrict__ scale,
                            const float* __restrict__ shift) {
    int tid = threadIdx.x;     // 256

    if (blockIdx.x == 0) {
        __shared__ float sred[NB][8];
        int warp = tid >> 5, lane = tid & 31;
        int s0 = __reduce_add_sync(0xffffffffu, mask[tid]);
        int s1 = __reduce_add_sync(0xffffffffu, mask[NL + tid]);
        if (lane == 0) { sred[0][warp] = (float)s0; sred[1][warp] = (float)s1; }
        __syncthreads();
        if (tid < NB * NC) {
            int b = tid >> 5, c = tid & 31;
            float nm = 0.f;
            #pragma unroll
            for (int i = 0; i < 8; ++i) nm += sred[b][i];
            float colsum = 0.f, tv[NA];
            #pragma unroll
            for (int a = 0; a < NA; ++a) { tv[a] = T[a * NC + c]; colsum += tv[a]; }
            float cntA = nm * (float)NA;
            float cnt  = fmaxf(cntA, 1.0f);
            float mean = (nm * colsum) / cnt;
            float ssqm = 0.f;
            #pragma unroll
            for (int a = 0; a < NA; ++a) {
                float d = tv[a] - mean;
                ssqm = fmaf(d, d, ssqm);
            }
            float ssq  = nm * ssqm + ((float)NATOM - cntA) * mean * mean;
            float rstd = rsqrtf(ssq / cnt + 1e-5f);
            float Ac   = rstd * scale[c];
            g_A[tid] = Ac;
            g_B[tid] = shift[c] - mean * Ac;
        }
    }

    // poison atoms (all blocks, grid-stride)
    for (int a = blockIdx.x * 256 + tid; a < NB * NATOM; a += PREP_BLOCKS * 256) {
        int b = a / NATOM;
        int j = a - b * NATOM;
        int m = mask[b * NL + j / NA];
        float4 v;
        float x = coords[a * 3 + 0], y = coords[a * 3 + 1], z = coords[a * 3 + 2];
        v.x = m ? x : POISON;
        v.y = m ? y : POISON;
        v.z = m ? z : POISON;
        v.w = (float)m;
        g_atoms[a] = v;
    }
}

// ---------------------------------------------------------------------------
// KNN: warp-per-row. Phase A reads global atoms (coalesced), caches keys in
// smem AND keeps per-lane register top-2 heads. Extraction: 2-redux on heads;
// owner invalidates popped slot in smem (STS INF); refill (E~7.7/row) rescans
// the owner's smem column.
// ---------------------------------------------------------------------------
__global__ void __launch_bounds__(THR, 3)
knn_kernel(const float* __restrict__ coords,
           const float* __restrict__ T,
           float* __restrict__ out) {
    extern __shared__ float s_d2[];                  // WARPS*32*97 = 74496 B

    int tid  = threadIdx.x;
    int warp = tid >> 5;
    int lane = tid & 31;

    int rowBase = blockIdx.x * WARPS;
    int b       = rowBase / NATOM;                   // blocks never straddle batches
    int row     = rowBase + warp;
    int ib      = row - b * NATOM;
    const float4* At = g_atoms + b * NATOM;

    float4 q = __ldg(&At[ib]);

    // ---- small outputs (encode / coords / mask) ----
    {
        int ty = ib % NA;
        float v = (q.w != 0.0f)
                    ? fmaf(__ldg(&T[ty * NC + lane]), g_A[b * NC + lane], g_B[b * NC + lane])
                    : 0.0f;
        out[O_ENC + row * NC + lane] = v;
    }
    if (tid < WARPS * 3) out[O_COORDS + rowBase * 3 + tid] = coords[rowBase * 3 + tid];
    if (tid < WARPS)     out[O_MASK + rowBase + tid] = __ldg(&At[rowBase - b * NATOM + tid].w);

    float* dist_out = out + O_DIST + row * KNB;
    float* idx_out  = out + O_IDX  + row * KNB;

    if (q.w == 0.0f) {                        // masked row -> pad outputs
        if (lane < KNB) {
            dist_out[lane] = BIGD;
            idx_out[lane]  = 0.0f;
        }
        return;
    }

    float* my = s_d2 + warp * (32 * TPAD);

    // ---- phase A: keys -> smem cache + branchless per-lane top-2 heads ----
    unsigned v0 = EMPTY_BITS, v1 = EMPTY_BITS;
    int i0 = 0, i1 = 0;
    #pragma unroll 8
    for (int t = 0; t < NT; ++t) {
        float4 a = __ldg(&At[t * 32 + lane]);
        float dx = q.x - a.x, dy = q.y - a.y, dz = q.z - a.z;
        float d2 = fmaf(dx, dx, fmaf(dy, dy, dz * dz));
        my[lane * TPAD + t] = d2;
        unsigned kb = __float_as_uint(d2);    // d2 >= 0 -> bits order-preserving
        int j = t * 32 + lane;
        bool lt1 = kb < v1;
        bool lt0 = kb < v0;                   // strict < keeps lowest-index tie order
        v1 = lt1 ? (lt0 ? v0 : kb) : v1;
        i1 = lt1 ? (lt0 ? i0 : j ) : i1;
        v0 = lt0 ? kb : v0;
        i0 = lt0 ? j  : i0;
    }

    // ---- extract-min x30 from the 32 lane-heads ----
    unsigned rvb = 0; int rj = 0;             // lane p holds pass-p result
    #pragma unroll 1
    for (int p = 0; p < KNB; ++p) {
        unsigned mvb = __reduce_min_sync(0xffffffffu, v0);
        unsigned cj  = (v0 == mvb) ? (unsigned)i0 : 0xFFFFFFFFu;
        unsigned mj  = __reduce_min_sync(0xffffffffu, cj);
        if (lane == p) { rvb = mvb; rj = (int)mj; }

        if (p < KNB - 1) {
            int w  = (int)(mj & 31u);
            int tm = (int)(mj >> 5);
            if (lane == w) {                  // owner: invalidate popped slot + pop
                my[w * TPAD + tm] = CUDART_INF_F;
                v0 = v1; i0 = i1; v1 = EMPTY_BITS;
            }
            bool empty = (lane == w) && (v0 == EMPTY_BITS);
            if (__ballot_sync(0xffffffffu, empty)) {
                // refill owner's head: cooperative 3-LDS rescan of column w
                __syncwarp();                 // make prior STS invalidations visible
                unsigned nvb = EMPTY_BITS;
                int nj = 0;
                #pragma unroll
                for (int s = 0; s < 3; ++s) {
                    int t = lane + s * 32;
                    float v = my[w * TPAD + t];
                    unsigned vb = __float_as_uint(v);
                    if (vb < nvb) { nvb = vb; nj = t * 32 + w; }
                }
                unsigned nmin = __reduce_min_sync(0xffffffffu, nvb);
                unsigned ncj  = (nvb == nmin) ? (unsigned)nj : 0xFFFFFFFFu;
                unsigned nidx = __reduce_min_sync(0xffffffffu, ncj);
                if (lane == w) { v0 = nmin; i0 = (int)nidx; }
            }
        }
    }

    if (lane < KNB) {
        float d2 = __uint_as_float(rvb);
        float dv = (d2 > 1e30f) ? BIGD : sqrtf(d2 + 1e-6f);
        dist_out[lane] = dv;
        idx_out[lane]  = (float)rj;
    }
}

// ---------------------------------------------------------------------------
extern "C" void kernel_launch(void* const* d_in, const int* in_sizes, int n_in,
                              void* d_out, int out_size) {
    const float* coords = (const float*)d_in[0];   // (2,256,12,3) f32
    const int*   mask   = (const int*)d_in[1];     // (2,256) i32
    const float* emb    = (const float*)d_in[2];   // (12,32) f32
    const float* scale  = (const float*)d_in[3];   // (1,1,32) f32
    const float* shift  = (const float*)d_in[4];   // (1,1,32) f32
    float* out = (float*)d_out;

    prep_kernel<<<PREP_BLOCKS, 256>>>(coords, mask, emb, scale, shift);

    int smem_bytes = WARPS * 32 * TPAD * 4;        // 74496
    cudaFuncSetAttribute(knn_kernel, cudaFuncAttributeMaxDynamicSharedMemorySize,
                         smem_bytes);
    int nblocks = (NB * NATOM) / WARPS;            // 1024
    knn_kernel<<<nblocks, THR, smem_bytes>>>(coords, emb, out);
}